// round 3
// baseline (speedup 1.0000x reference)
#include <cuda_runtime.h>

#define BATCH 4096
#define FEAT  4096

// scratch (device-global; no allocation allowed in kernel_launch)
__device__ float g_row_hinge[BATCH];
__device__ unsigned int g_done;   // zero-initialized at module load; reset by last block

__global__ void __launch_bounds__(256) myloss_fused_kernel(
    const float* __restrict__ out1,
    const float* __restrict__ out2,
    const float* __restrict__ out3,
    float* __restrict__ out)
{
    const int row = blockIdx.x;
    const size_t base = (size_t)row * FEAT;
    const float4* __restrict__ p1 = reinterpret_cast<const float4*>(out1 + base);
    const float4* __restrict__ p2 = reinterpret_cast<const float4*>(out2 + base);
    const float4* __restrict__ p3 = reinterpret_cast<const float4*>(out3 + base);

    float s13 = 0.0f;  // sum (o1-o3)^2
    float s12 = 0.0f;  // sum (o1-o2)^2

    // FEAT/4 = 1024 float4 per row; 256 threads -> 4 iterations each.
    #pragma unroll
    for (int it = 0; it < (FEAT / 4) / 256; ++it) {
        const int i = it * 256 + threadIdx.x;
        float4 a = p1[i];
        float4 b = p2[i];
        float4 c = p3[i];
        float d;
        d = a.x - c.x; s13 = fmaf(d, d, s13);
        d = a.y - c.y; s13 = fmaf(d, d, s13);
        d = a.z - c.z; s13 = fmaf(d, d, s13);
        d = a.w - c.w; s13 = fmaf(d, d, s13);
        d = a.x - b.x; s12 = fmaf(d, d, s12);
        d = a.y - b.y; s12 = fmaf(d, d, s12);
        d = a.z - b.z; s12 = fmaf(d, d, s12);
        d = a.w - b.w; s12 = fmaf(d, d, s12);
    }

    // warp reduction of both sums
    #pragma unroll
    for (int off = 16; off > 0; off >>= 1) {
        s13 += __shfl_xor_sync(0xFFFFFFFFu, s13, off);
        s12 += __shfl_xor_sync(0xFFFFFFFFu, s12, off);
    }

    __shared__ float sh13[8];
    __shared__ float sh12[8];
    __shared__ bool  is_last;
    const int lane = threadIdx.x & 31;
    const int wid  = threadIdx.x >> 5;
    if (lane == 0) { sh13[wid] = s13; sh12[wid] = s12; }
    __syncthreads();

    if (threadIdx.x == 0) {
        float a13 = 0.0f, a12 = 0.0f;
        #pragma unroll
        for (int w = 0; w < 8; ++w) { a13 += sh13[w]; a12 += sh12[w]; }
        float compare = 2.0f - sqrtf(a13) + sqrtf(a12);
        g_row_hinge[row] = fmaxf(0.0f, compare);
        __threadfence();                       // make hinge visible before counting
        unsigned int t = atomicAdd(&g_done, 1u);
        is_last = (t == (unsigned int)(BATCH - 1));
    }
    __syncthreads();

    // Last-arriving CTA performs the final reduction (g_row_hinge is L2-hot).
    if (is_last) {
        float s = 0.0f;
        #pragma unroll
        for (int it = 0; it < BATCH / 256; ++it)
            s += g_row_hinge[it * 256 + threadIdx.x];

        #pragma unroll
        for (int off = 16; off > 0; off >>= 1)
            s += __shfl_xor_sync(0xFFFFFFFFu, s, off);

        __shared__ float shf[8];
        if (lane == 0) shf[wid] = s;
        __syncthreads();

        if (threadIdx.x == 0) {
            float tot = 0.0f;
            #pragma unroll
            for (int w = 0; w < 8; ++w) tot += shf[w];
            out[0] = tot * (float)BATCH;       // [B,B] broadcast -> scale by B
            g_done = 0;                        // reset for next graph replay
        }
    }
}

extern "C" void kernel_launch(void* const* d_in, const int* in_sizes, int n_in,
                              void* d_out, int out_size)
{
    const float* out1 = (const float*)d_in[0];
    const float* out2 = (const float*)d_in[1];
    const float* out3 = (const float*)d_in[2];
    float* out = (float*)d_out;

    myloss_fused_kernel<<<BATCH, 256>>>(out1, out2, out3, out);
}

// round 4
// speedup vs baseline: 1.0643x; 1.0643x over previous
#include <cuda_runtime.h>

#define BATCH 4096
#define FEAT  4096

// per-row hinge values (scratch — no device allocation allowed in kernel_launch)
__device__ float g_row_hinge[BATCH];

__global__ void __launch_bounds__(256) row_dist_kernel(
    const float* __restrict__ out1,
    const float* __restrict__ out2,
    const float* __restrict__ out3)
{
    const int row = blockIdx.x;
    const size_t base = (size_t)row * FEAT;
    const float4* __restrict__ p1 = reinterpret_cast<const float4*>(out1 + base);
    const float4* __restrict__ p2 = reinterpret_cast<const float4*>(out2 + base);
    const float4* __restrict__ p3 = reinterpret_cast<const float4*>(out3 + base);

    float s13 = 0.0f;  // sum (o1-o3)^2
    float s12 = 0.0f;  // sum (o1-o2)^2

    // FEAT/4 = 1024 float4 per row; 256 threads -> 4 iterations each.
    // __ldcs: streamed once, evict-first (no L2 retention benefit here).
    #pragma unroll
    for (int it = 0; it < (FEAT / 4) / 256; ++it) {
        const int i = it * 256 + threadIdx.x;
        float4 a = __ldcs(p1 + i);
        float4 b = __ldcs(p2 + i);
        float4 c = __ldcs(p3 + i);
        float d;
        d = a.x - c.x; s13 = fmaf(d, d, s13);
        d = a.y - c.y; s13 = fmaf(d, d, s13);
        d = a.z - c.z; s13 = fmaf(d, d, s13);
        d = a.w - c.w; s13 = fmaf(d, d, s13);
        d = a.x - b.x; s12 = fmaf(d, d, s12);
        d = a.y - b.y; s12 = fmaf(d, d, s12);
        d = a.z - b.z; s12 = fmaf(d, d, s12);
        d = a.w - b.w; s12 = fmaf(d, d, s12);
    }

    // warp reduction of both sums
    #pragma unroll
    for (int off = 16; off > 0; off >>= 1) {
        s13 += __shfl_xor_sync(0xFFFFFFFFu, s13, off);
        s12 += __shfl_xor_sync(0xFFFFFFFFu, s12, off);
    }

    __shared__ float sh13[8];
    __shared__ float sh12[8];
    const int lane = threadIdx.x & 31;
    const int wid  = threadIdx.x >> 5;
    if (lane == 0) { sh13[wid] = s13; sh12[wid] = s12; }
    __syncthreads();

    if (threadIdx.x == 0) {
        float a13 = 0.0f, a12 = 0.0f;
        #pragma unroll
        for (int w = 0; w < 8; ++w) { a13 += sh13[w]; a12 += sh12[w]; }
        float compare = 2.0f - sqrtf(a13) + sqrtf(a12);
        g_row_hinge[row] = fmaxf(0.0f, compare);
    }
}

__global__ void __launch_bounds__(1024) final_reduce_kernel(float* __restrict__ out)
{
    // PDL: wait until the primary grid's memory is visible before reading.
    cudaGridDependencySynchronize();

    // 1024 threads x 1 float4 = 4096 floats, exactly BATCH.
    const float4 v = reinterpret_cast<const float4*>(g_row_hinge)[threadIdx.x];
    float s = (v.x + v.y) + (v.z + v.w);

    #pragma unroll
    for (int off = 16; off > 0; off >>= 1)
        s += __shfl_xor_sync(0xFFFFFFFFu, s, off);

    __shared__ float sh[32];
    const int lane = threadIdx.x & 31;
    const int wid  = threadIdx.x >> 5;
    if (lane == 0) sh[wid] = s;
    __syncthreads();

    if (wid == 0) {
        s = sh[lane];
        #pragma unroll
        for (int off = 16; off > 0; off >>= 1)
            s += __shfl_xor_sync(0xFFFFFFFFu, s, off);
        if (lane == 0)
            out[0] = s * (float)BATCH;  // [B,B] broadcast -> scale by B
    }
}

extern "C" void kernel_launch(void* const* d_in, const int* in_sizes, int n_in,
                              void* d_out, int out_size)
{
    const float* out1 = (const float*)d_in[0];
    const float* out2 = (const float*)d_in[1];
    const float* out3 = (const float*)d_in[2];
    float* out = (float*)d_out;

    row_dist_kernel<<<BATCH, 256>>>(out1, out2, out3);

    // Secondary launch with programmatic stream serialization (PDL):
    // its launch latency overlaps the primary kernel's execution.
    cudaLaunchConfig_t cfg = {};
    cfg.gridDim  = dim3(1, 1, 1);
    cfg.blockDim = dim3(1024, 1, 1);
    cfg.dynamicSmemBytes = 0;
    cfg.stream = 0;  // legacy default stream (same as <<<>>> above)

    cudaLaunchAttribute attr[1];
    attr[0].id = cudaLaunchAttributeProgrammaticStreamSerialization;
    attr[0].val.programmaticStreamSerializationAllowed = 1;
    cfg.attrs = attr;
    cfg.numAttrs = 1;

    cudaLaunchKernelEx(&cfg, final_reduce_kernel, out);
}